// round 10
// baseline (speedup 1.0000x reference)
#include <cuda_runtime.h>
#include <cuda_bf16.h>
#include <math.h>
#include <float.h>
#include <stdint.h>

// ---------------- problem constants ----------------
#define BATCH   4
#define QLEN    128
#define HDIM    4096
#define NHEAD   32
#define NKVH    8
#define DHEAD   128
#define KVDIM   1024
#define TOK     512
#define NQK     4096
#define RESLEN  128
#define KVSEQ   4352
#define PASTLEN 4224
#define NBLK    68
#define NEGF    (-3.402823466e38f)

// ---------------- scratch ----------------
__device__ float g_qlin[TOK * HDIM];
__device__ float g_klin[TOK * KVDIM];
__device__ float g_vlin[TOK * KVDIM];
__device__ float g_q   [BATCH * NHEAD * QLEN * DHEAD];

__device__ __nv_bfloat16 g_hshi[TOK * HDIM],  g_hslo[TOK * HDIM];
__device__ __nv_bfloat16 g_qwhi[HDIM * HDIM], g_qwlo[HDIM * HDIM];
__device__ __nv_bfloat16 g_kwhi[KVDIM * HDIM], g_kwlo[KVDIM * HDIM];
__device__ __nv_bfloat16 g_vwhi[KVDIM * HDIM], g_vwlo[KVDIM * HDIM];
__device__ __nv_bfloat16 g_owhi[HDIM * HDIM], g_owlo[HDIM * HDIM];
__device__ __nv_bfloat16 g_khi [BATCH * NKVH * KVSEQ * DHEAD];
__device__ __nv_bfloat16 g_klo [BATCH * NKVH * KVSEQ * DHEAD];
__device__ __nv_bfloat16 g_vthi[BATCH * NKVH * DHEAD * KVSEQ];
__device__ __nv_bfloat16 g_vtlo[BATCH * NKVH * DHEAD * KVSEQ];
__device__ __nv_bfloat16 g_aohi[TOK * HDIM],  g_aolo[TOK * HDIM];

// ---------------- helpers ----------------
__device__ __forceinline__ void mma16816(float* c, const uint32_t* a, const uint32_t* b) {
    asm volatile(
        "mma.sync.aligned.m16n8k16.row.col.f32.bf16.bf16.f32 "
        "{%0,%1,%2,%3}, {%4,%5,%6,%7}, {%8,%9}, {%0,%1,%2,%3};"
        : "+f"(c[0]), "+f"(c[1]), "+f"(c[2]), "+f"(c[3])
        : "r"(a[0]), "r"(a[1]), "r"(a[2]), "r"(a[3]), "r"(b[0]), "r"(b[1]));
}
__device__ __forceinline__ uint32_t packb(__nv_bfloat16 a, __nv_bfloat16 b) {
    __nv_bfloat162 p(a, b);
    return *(uint32_t*)&p;
}
__device__ __forceinline__ void split2(float x0, float x1, uint32_t& hi, uint32_t& lo) {
    __nv_bfloat16 h0 = __float2bfloat16(x0), h1 = __float2bfloat16(x1);
    hi = packb(h0, h1);
    lo = packb(__float2bfloat16(x0 - __bfloat162float(h0)),
               __float2bfloat16(x1 - __bfloat162float(h1)));
}
__device__ __forceinline__ void cp16(void* s, const void* g) {
    uint32_t sa = (uint32_t)__cvta_generic_to_shared(s);
    asm volatile("cp.async.cg.shared.global [%0], [%1], 16;" :: "r"(sa), "l"(g));
}

// ---------------- fp32 -> bf16 hi/lo splitter ---------------------------------
__global__ __launch_bounds__(256) void split_f32(
    const float* __restrict__ in, __nv_bfloat16* __restrict__ hi,
    __nv_bfloat16* __restrict__ lo)
{
    int i = (blockIdx.x * 256 + threadIdx.x) * 4;
    float4 v = *(const float4*)(in + i);
    uint32_t h0, l0, h1, l1;
    split2(v.x, v.y, h0, l0);
    split2(v.z, v.w, h1, l1);
    uint2 H; H.x = h0; H.y = h1;
    uint2 L; L.x = l0; L.y = l1;
    *(uint2*)(hi + i) = H;
    *(uint2*)(lo + i) = L;
}

// ---------------- pipelined GEMM core, 256x128 C tile -------------------------
#define PITCH 72
#define A_TILE (256 * PITCH)                       // 18432 elems
#define B_TILE (128 * PITCH)                       // 9216 elems
#define STAGE_ELEMS (2 * A_TILE + 2 * B_TILE)      // 55296 elems
#define S_GEMM (2 * STAGE_ELEMS * 2)               // 221184 B

__device__ __forceinline__ void gemm_core256(
    const __nv_bfloat16* __restrict__ Ahi, const __nv_bfloat16* __restrict__ Alo,
    const __nv_bfloat16* __restrict__ Bhi, const __nv_bfloat16* __restrict__ Blo,
    const float* __restrict__ bias, float* __restrict__ C,
    int lda, int ldb, int ldc, int K, __nv_bfloat16* sm)
{
    const int tid  = threadIdx.x;
    const int lane = tid & 31;
    const int wid  = tid >> 5;
    const int wm   = wid >> 2;          // 0..1 -> 128 rows each
    const int wn   = wid & 3;

    float acc[8][4][4];
#pragma unroll
    for (int mt = 0; mt < 8; mt++)
#pragma unroll
        for (int nt = 0; nt < 4; nt++)
#pragma unroll
            for (int i = 0; i < 4; i++) acc[mt][nt][i] = 0.f;

    const int nch = K >> 6;

#define G_STAGE(ch, buf) do {                                              \
    __nv_bfloat16* aH = sm + (buf) * STAGE_ELEMS;                          \
    __nv_bfloat16* aL = aH + A_TILE;                                       \
    __nv_bfloat16* bH = aH + 2 * A_TILE;                                   \
    __nv_bfloat16* bL = bH + B_TILE;                                       \
    const int k0 = (ch) << 6;                                              \
    _Pragma("unroll")                                                      \
    for (int i = 0; i < 8; i++) {                                          \
        int u = i * 256 + tid;                                             \
        int r = u >> 3, kp = (u & 7) * 8, so = r * PITCH + kp;             \
        cp16(aH + so, Ahi + (size_t)r * lda + k0 + kp);                    \
        cp16(aL + so, Alo + (size_t)r * lda + k0 + kp);                    \
    }                                                                      \
    _Pragma("unroll")                                                      \
    for (int i = 0; i < 4; i++) {                                          \
        int u = i * 256 + tid;                                             \
        int r = u >> 3, kp = (u & 7) * 8, so = r * PITCH + kp;             \
        cp16(bH + so, Bhi + (size_t)r * ldb + k0 + kp);                    \
        cp16(bL + so, Blo + (size_t)r * ldb + k0 + kp);                    \
    }                                                                      \
    asm volatile("cp.async.commit_group;");                                \
} while (0)

    G_STAGE(0, 0);
    for (int ch = 0; ch < nch; ch++) {
        if (ch + 1 < nch) {
            G_STAGE(ch + 1, (ch + 1) & 1);
            asm volatile("cp.async.wait_group 1;");
        } else {
            asm volatile("cp.async.wait_group 0;");
        }
        __syncthreads();

        const __nv_bfloat16* sAhi = sm + (ch & 1) * STAGE_ELEMS;
        const __nv_bfloat16* sAlo = sAhi + A_TILE;
        const __nv_bfloat16* sBhi = sAhi + 2 * A_TILE;
        const __nv_bfloat16* sBlo = sBhi + B_TILE;

#pragma unroll
        for (int ks = 0; ks < 4; ks++) {
            const int kb = ks * 16 + (lane & 3) * 2;
            uint32_t bh[4][2], bl[4][2];
            const int nrow = wn * 32 + (lane >> 2);
#pragma unroll
            for (int nt = 0; nt < 4; nt++) {
                int nb = (nrow + nt * 8) * PITCH + kb;
                bh[nt][0] = *(uint32_t*)&sBhi[nb];
                bh[nt][1] = *(uint32_t*)&sBhi[nb + 8];
                bl[nt][0] = *(uint32_t*)&sBlo[nb];
                bl[nt][1] = *(uint32_t*)&sBlo[nb + 8];
            }
            const int arow = wm * 128 + (lane >> 2);
#pragma unroll
            for (int mt = 0; mt < 8; mt++) {
                int ab = (arow + mt * 16) * PITCH + kb;
                uint32_t ah[4], al[4];
                ah[0] = *(uint32_t*)&sAhi[ab];
                ah[1] = *(uint32_t*)&sAhi[ab + 8 * PITCH];
                ah[2] = *(uint32_t*)&sAhi[ab + 8];
                ah[3] = *(uint32_t*)&sAhi[ab + 8 * PITCH + 8];
                al[0] = *(uint32_t*)&sAlo[ab];
                al[1] = *(uint32_t*)&sAlo[ab + 8 * PITCH];
                al[2] = *(uint32_t*)&sAlo[ab + 8];
                al[3] = *(uint32_t*)&sAlo[ab + 8 * PITCH + 8];
#pragma unroll
                for (int nt = 0; nt < 4; nt++) {
                    mma16816(acc[mt][nt], ah, bh[nt]);
                    mma16816(acc[mt][nt], ah, bl[nt]);
                    mma16816(acc[mt][nt], al, bh[nt]);
                }
            }
        }
        __syncthreads();
    }
#undef G_STAGE

    const int r0 = wm * 128 + (lane >> 2);
    const int c0 = wn * 32 + (lane & 3) * 2;
#pragma unroll
    for (int mt = 0; mt < 8; mt++) {
#pragma unroll
        for (int nt = 0; nt < 4; nt++) {
            int cc = c0 + nt * 8;
#pragma unroll
            for (int half = 0; half < 2; half++) {
                int r = r0 + mt * 16 + half * 8;
                float2 o;
                o.x = acc[mt][nt][half * 2 + 0];
                o.y = acc[mt][nt][half * 2 + 1];
                if (bias) {
                    o.x += bias[cc];
                    o.y += bias[cc + 1];
                }
                *(float2*)(C + (size_t)r * ldc + cc) = o;
            }
        }
    }
}

// ---------------- merged QKV projection (96 CTAs, one wave) -------------------
__global__ __launch_bounds__(256, 1) void proj_qkv(
    const float* __restrict__ qb, const float* __restrict__ kb,
    const float* __restrict__ vb)
{
    extern __shared__ __nv_bfloat16 sm[];
    const int x = blockIdx.x;          // 0..47
    const int y = blockIdx.y;          // 0..1 (256 rows each)
    const __nv_bfloat16 *Bh, *Bl;
    const float* bias;
    float* C;
    int N, tx;
    if (x < 32)      { tx = x;      Bh = g_qwhi; Bl = g_qwlo; bias = qb; C = g_qlin; N = HDIM; }
    else if (x < 40) { tx = x - 32; Bh = g_kwhi; Bl = g_kwlo; bias = kb; C = g_klin; N = KVDIM; }
    else             { tx = x - 40; Bh = g_vwhi; Bl = g_vwlo; bias = vb; C = g_vlin; N = KVDIM; }

    const size_t arow0 = (size_t)y * 256;
    const size_t brow0 = (size_t)tx * 128;
    gemm_core256(g_hshi + arow0 * HDIM, g_hslo + arow0 * HDIM,
                 Bh + brow0 * HDIM, Bl + brow0 * HDIM,
                 bias + brow0, C + arow0 * N + brow0,
                 HDIM, HDIM, N, HDIM, sm);
}

// ---------------- O projection ------------------------------------------------
__global__ __launch_bounds__(256, 1) void gemm_single(
    const __nv_bfloat16* __restrict__ Ahi, const __nv_bfloat16* __restrict__ Alo,
    const __nv_bfloat16* __restrict__ Bhi, const __nv_bfloat16* __restrict__ Blo,
    const float* __restrict__ bias, float* __restrict__ C,
    int lda, int ldb, int ldc, int K)
{
    extern __shared__ __nv_bfloat16 sm[];
    const size_t arow0 = (size_t)(blockIdx.y * 256);
    const size_t brow0 = (size_t)(blockIdx.x * 128);
    gemm_core256(Ahi + arow0 * lda, Alo + arow0 * lda,
                 Bhi + brow0 * ldb, Blo + brow0 * ldb,
                 bias ? bias + brow0 : nullptr, C + arow0 * ldc + brow0,
                 lda, ldb, ldc, K, sm);
}

// ---------------- fused flash attention (3-stage cp.async) --------------------
#define FK_PITCH 136
#define FV_PITCH 72
#define FBUF_ELEMS (2 * 64 * FK_PITCH + 2 * 128 * FV_PITCH)   // 35840 elems
#define S_FLASH (3 * FBUF_ELEMS * 2)                          // 215040 B

__global__ __launch_bounds__(256, 1) void flash_attn()
{
    extern __shared__ __nv_bfloat16 fsm[];

    const int bh = blockIdx.x;
    const int b = bh >> 5, h = bh & 31, kvh = h >> 2;
    const int bk = b * NKVH + kvh;
    const int tid = threadIdx.x, lane = tid & 31, w = tid >> 5;
    const int rq = w * 16 + (lane >> 2);
    const int q2 = (lane & 3) * 2;
    const float isq = 0.08838834764831845f;

    const float* Q = g_q + (size_t)bh * QLEN * DHEAD;
    uint32_t qhi[8][4], qlo[8][4];
#pragma unroll
    for (int kk = 0; kk < 8; kk++) {
#pragma unroll
        for (int f = 0; f < 4; f++) {
            int rr = rq + ((f & 1) ? 8 : 0);
            int kc = kk * 16 + ((f & 2) ? 8 : 0) + q2;
            split2(Q[rr * DHEAD + kc], Q[rr * DHEAD + kc + 1], qhi[kk][f], qlo[kk][f]);
        }
    }

    const __nv_bfloat16* Khi = g_khi + (size_t)bk * KVSEQ * DHEAD;
    const __nv_bfloat16* Klo = g_klo + (size_t)bk * KVSEQ * DHEAD;
    const __nv_bfloat16* Vhi = g_vthi + (size_t)bk * DHEAD * KVSEQ;
    const __nv_bfloat16* Vlo = g_vtlo + (size_t)bk * DHEAD * KVSEQ;

    float m0 = NEGF, m1 = NEGF, l0 = 0.f, l1 = 0.f;
    float oacc[16][4];
#pragma unroll
    for (int td = 0; td < 16; td++)
#pragma unroll
        for (int i = 0; i < 4; i++) oacc[td][i] = 0.f;

#define F_STAGE(j, buf) do {                                               \
    __nv_bfloat16* dKhi = fsm + (buf) * FBUF_ELEMS;                        \
    __nv_bfloat16* dKlo = dKhi + 64 * FK_PITCH;                            \
    __nv_bfloat16* dVhi = dKhi + 2 * 64 * FK_PITCH;                        \
    __nv_bfloat16* dVlo = dVhi + 128 * FV_PITCH;                           \
    _Pragma("unroll")                                                      \
    for (int i = 0; i < 4; i++) {                                          \
        int u = i * 256 + tid;                                             \
        int n = u >> 4, kp = (u & 15) * 8;                                 \
        size_t go = (size_t)((j) * 64 + n) * DHEAD + kp;                   \
        cp16(dKhi + n * FK_PITCH + kp, Khi + go);                          \
        cp16(dKlo + n * FK_PITCH + kp, Klo + go);                          \
        int d = u >> 3, vp = (u & 7) * 8;                                  \
        size_t gv = (size_t)d * KVSEQ + (j) * 64 + vp;                     \
        cp16(dVhi + d * FV_PITCH + vp, Vhi + gv);                          \
        cp16(dVlo + d * FV_PITCH + vp, Vlo + gv);                          \
    }                                                                      \
    asm volatile("cp.async.commit_group;");                                \
} while (0)

    F_STAGE(0, 0);
    F_STAGE(1, 1);
    int buf = 0;
    for (int j = 0; j < NBLK; j++) {
        if (j + 2 < NBLK) {
            int b2 = buf + 2; if (b2 >= 3) b2 -= 3;
            F_STAGE(j + 2, b2);
            asm volatile("cp.async.wait_group 2;");
        } else if (j + 1 < NBLK) {
            asm volatile("cp.async.wait_group 1;");
        } else {
            asm volatile("cp.async.wait_group 0;");
        }
        __syncthreads();

        const __nv_bfloat16* sKhi = fsm + buf * FBUF_ELEMS;
        const __nv_bfloat16* sKlo = sKhi + 64 * FK_PITCH;
        const __nv_bfloat16* sVhi = sKhi + 2 * 64 * FK_PITCH;
        const __nv_bfloat16* sVlo = sVhi + 128 * FV_PITCH;

        float sacc[8][4];
#pragma unroll
        for (int nt = 0; nt < 8; nt++)
#pragma unroll
            for (int i = 0; i < 4; i++) sacc[nt][i] = 0.f;

#pragma unroll
        for (int kk = 0; kk < 8; kk++) {
            const int kb = kk * 16 + q2;
#pragma unroll
            for (int nt = 0; nt < 8; nt++) {
                int nb = (nt * 8 + (lane >> 2)) * FK_PITCH + kb;
                uint32_t bhf[2], blf[2];
                bhf[0] = *(uint32_t*)&sKhi[nb];
                bhf[1] = *(uint32_t*)&sKhi[nb + 8];
                blf[0] = *(uint32_t*)&sKlo[nb];
                blf[1] = *(uint32_t*)&sKlo[nb + 8];
                mma16816(sacc[nt], qhi[kk], bhf);
                mma16816(sacc[nt], qhi[kk], blf);
                mma16816(sacc[nt], qlo[kk], bhf);
            }
        }

#pragma unroll
        for (int nt = 0; nt < 8; nt++)
#pragma unroll
            for (int i = 0; i < 4; i++) sacc[nt][i] *= isq;
        if (j >= 66) {
            int jc = j * 64 - PASTLEN;
#pragma unroll
            for (int nt = 0; nt < 8; nt++) {
                int c = jc + nt * 8 + q2;
                if (c     > rq)     sacc[nt][0] = NEGF;
                if (c + 1 > rq)     sacc[nt][1] = NEGF;
                if (c     > rq + 8) sacc[nt][2] = NEGF;
                if (c + 1 > rq + 8) sacc[nt][3] = NEGF;
            }
        }

        float mx0 = NEGF, mx1 = NEGF;
#pragma unroll
        for (int nt = 0; nt < 8; nt++) {
            mx0 = fmaxf(mx0, fmaxf(sacc[nt][0], sacc[nt][1]));
            mx1 = fmaxf(mx1, fmaxf(sacc[nt][2], sacc[nt][3]));
        }
        mx0 = fmaxf(mx0, __shfl_xor_sync(0xffffffffu, mx0, 1));
        mx0 = fmaxf(mx0, __shfl_xor_sync(0xffffffffu, mx0, 2));
        mx1 = fmaxf(mx1, __shfl_xor_sync(0xffffffffu, mx1, 1));
        mx1 = fmaxf(mx1, __shfl_xor_sync(0xffffffffu, mx1, 2));

        float mn0 = fmaxf(m0, mx0), mn1 = fmaxf(m1, mx1);
        float a0 = __expf(m0 - mn0), a1 = __expf(m1 - mn1);

        float rs0 = 0.f, rs1 = 0.f;
#pragma unroll
        for (int nt = 0; nt < 8; nt++) {
            sacc[nt][0] = __expf(sacc[nt][0] - mn0);
            sacc[nt][1] = __expf(sacc[nt][1] - mn0);
            sacc[nt][2] = __expf(sacc[nt][2] - mn1);
            sacc[nt][3] = __expf(sacc[nt][3] - mn1);
            rs0 += sacc[nt][0] + sacc[nt][1];
            rs1 += sacc[nt][2] + sacc[nt][3];
        }
        rs0 += __shfl_xor_sync(0xffffffffu, rs0, 1);
        rs0 += __shfl_xor_sync(0xffffffffu, rs0, 2);
        rs1 += __shfl_xor_sync(0xffffffffu, rs1, 1);
        rs1 += __shfl_xor_sync(0xffffffffu, rs1, 2);
        l0 = l0 * a0 + rs0;
        l1 = l1 * a1 + rs1;
        m0 = mn0; m1 = mn1;

#pragma unroll
        for (int td = 0; td < 16; td++) {
            oacc[td][0] *= a0; oacc[td][1] *= a0;
            oacc[td][2] *= a1; oacc[td][3] *= a1;
        }

#pragma unroll
        for (int kk2 = 0; kk2 < 4; kk2++) {
            uint32_t phi[4], plo[4];
            split2(sacc[2 * kk2][0],     sacc[2 * kk2][1],     phi[0], plo[0]);
            split2(sacc[2 * kk2][2],     sacc[2 * kk2][3],     phi[1], plo[1]);
            split2(sacc[2 * kk2 + 1][0], sacc[2 * kk2 + 1][1], phi[2], plo[2]);
            split2(sacc[2 * kk2 + 1][2], sacc[2 * kk2 + 1][3], phi[3], plo[3]);
            const int kb = kk2 * 16 + q2;
#pragma unroll
            for (int td = 0; td < 16; td++) {
                int vb = (td * 8 + (lane >> 2)) * FV_PITCH + kb;
                uint32_t vbh[2], vbl[2];
                vbh[0] = *(uint32_t*)&sVhi[vb];
                vbh[1] = *(uint32_t*)&sVhi[vb + 8];
                vbl[0] = *(uint32_t*)&sVlo[vb];
                vbl[1] = *(uint32_t*)&sVlo[vb + 8];
                mma16816(oacc[td], phi, vbh);
                mma16816(oacc[td], phi, vbl);
                mma16816(oacc[td], plo, vbh);
            }
        }
        __syncthreads();
        if (++buf == 3) buf = 0;
    }
#undef F_STAGE

    float inv0 = 1.f / l0, inv1 = 1.f / l1;
#pragma unroll
    for (int td = 0; td < 16; td++) {
        int cd = h * DHEAD + td * 8 + q2;
        {
            float x0 = oacc[td][0] * inv0, x1 = oacc[td][1] * inv0;
            uint32_t hi, lo;
            split2(x0, x1, hi, lo);
            size_t o = (size_t)(b * QLEN + rq) * HDIM + cd;
            *(uint32_t*)&g_aohi[o] = hi;
            *(uint32_t*)&g_aolo[o] = lo;
        }
        {
            float x0 = oacc[td][2] * inv1, x1 = oacc[td][3] * inv1;
            uint32_t hi, lo;
            split2(x0, x1, hi, lo);
            size_t o = (size_t)(b * QLEN + rq + 8) * HDIM + cd;
            *(uint32_t*)&g_aohi[o] = hi;
            *(uint32_t*)&g_aolo[o] = lo;
        }
    }
}

// ---------------- RoPE Q ------------------------------------------------------
__global__ __launch_bounds__(256) void rope_q_kernel()
{
    int idx = blockIdx.x * 256 + threadIdx.x;
    int d = idx & 127;
    int t = (idx >> 7) & 127;
    int h = (idx >> 14) & 31;
    int b = idx >> 19;
    size_t base = ((size_t)(b * QLEN + t)) * HDIM + (size_t)h * DHEAD;
    int i = d & 63;
    float inv = 1.0f / powf(1.0e6f, (float)(2 * i) / 128.0f);
    float ang = (float)(PASTLEN + t) * inv;
    float s, c;
    sincosf(ang, &s, &c);
    float x  = g_qlin[base + d];
    float xo = g_qlin[base + ((d < 64) ? d + 64 : d - 64)];
    g_q[idx] = (d < 64) ? (x * c - xo * s) : (x * c + xo * s);
}

// ---------------- merged RoPE-K + V-scatter (new tokens) ----------------------
__global__ __launch_bounds__(256) void rope_kv_kernel()
{
    int idx = blockIdx.x * 256 + threadIdx.x;      // 4*8*128*128
    // K part: d inner
    {
        int d   = idx & 127;
        int t   = (idx >> 7) & 127;
        int kvh = (idx >> 14) & 7;
        int b   = idx >> 17;
        size_t base = ((size_t)(b * QLEN + t)) * KVDIM + (size_t)kvh * DHEAD;
        int i = d & 63;
        float inv = 1.0f / powf(1.0e6f, (float)(2 * i) / 128.0f);
        float ang = (float)(PASTLEN + t) * inv;
        float s, c;
        sincosf(ang, &s, &c);
        float x  = g_klin[base + d];
        float xo = g_klin[base + ((d < 64) ? d + 64 : d - 64)];
        float v  = (d < 64) ? (x * c - xo * s) : (x * c + xo * s);
        size_t o = (((size_t)(b * NKVH + kvh)) * KVSEQ + PASTLEN + t) * DHEAD + d;
        __nv_bfloat16 hi = __float2bfloat16(v);
        g_khi[o] = hi;
        g_klo[o] = __float2bfloat16(v - __bfloat162float(hi));
    }
    // V part: t inner (coalesced along kv for transposed store)
    {
        int t   = idx & 127;
        int d   = (idx >> 7) & 127;
        int kvh = (idx >> 14) & 7;
        int b   = idx >> 17;
        float v = g_vlin[((size_t)(b * QLEN + t)) * KVDIM + kvh * DHEAD + d];
        size_t o = ((size_t)(b * NKVH + kvh) * DHEAD + d) * KVSEQ + PASTLEN + t;
        __nv_bfloat16 hi = __float2bfloat16(v);
        g_vthi[o] = hi;
        g_vtlo[o] = __float2bfloat16(v - __bfloat162float(hi));
    }
}

// ---------------- fp32 past copy (split) --------------------------------------
__global__ __launch_bounds__(256) void past_copy_kernel(
    const float* __restrict__ kfp, const float* __restrict__ vfp)
{
    int idx = blockIdx.x * 256 + threadIdx.x;      // 32*128*128
    int d  = idx & 127;
    int r  = (idx >> 7) & 127;
    int bk = idx >> 14;
    size_t src = ((size_t)bk * RESLEN + r) * DHEAD + d;
    if (blockIdx.y == 0) {
        float v = kfp[src];
        size_t o = ((size_t)bk * KVSEQ + NQK + r) * DHEAD + d;
        __nv_bfloat16 hi = __float2bfloat16(v);
        g_khi[o] = hi;
        g_klo[o] = __float2bfloat16(v - __bfloat162float(hi));
    } else {
        float v = vfp[src];
        size_t o = ((size_t)bk * DHEAD + d) * KVSEQ + NQK + r;
        __nv_bfloat16 hi = __float2bfloat16(v);
        g_vthi[o] = hi;
        g_vtlo[o] = __float2bfloat16(v - __bfloat162float(hi));
    }
}

// ---------------- dequant 2-bit K -> split K cache ----------------------------
__global__ __launch_bounds__(256) void dequant_k_kernel(
    const int* __restrict__ kq, const float* __restrict__ ks,
    const float* __restrict__ km)
{
    int idx = blockIdx.x * 256 + threadIdx.x;
    int d  = idx & 127;
    int n  = (idx >> 7) & 4095;
    int bk = idx >> 19;
    unsigned word = (unsigned)kq[((size_t)bk * DHEAD + d) * (NQK / 16) + (n >> 4)];
    float code = (float)((word >> ((n & 15) * 2)) & 3u);
    size_t sidx = ((size_t)bk * DHEAD + d) * (NQK / 64) + (n >> 6);
    float v = code * ks[sidx] + km[sidx];
    size_t o = ((size_t)bk * KVSEQ + n) * DHEAD + d;
    __nv_bfloat16 hi = __float2bfloat16(v);
    g_khi[o] = hi;
    g_klo[o] = __float2bfloat16(v - __bfloat162float(hi));
}

// ---------------- dequant 2-bit V -> split V^T cache --------------------------
__global__ __launch_bounds__(256) void dequant_v_kernel(
    const int* __restrict__ vq, const float* __restrict__ vs,
    const float* __restrict__ vm)
{
    int idx = blockIdx.x * 256 + threadIdx.x;
    int n  = idx & 4095;
    int d  = (idx >> 12) & 127;
    int bk = idx >> 19;
    unsigned word = (unsigned)vq[((size_t)bk * NQK + n) * (DHEAD / 16) + (d >> 4)];
    float code = (float)((word >> ((d & 15) * 2)) & 3u);
    size_t sidx = ((size_t)bk * NQK + n) * (DHEAD / 64) + (d >> 6);
    float v = code * vs[sidx] + vm[sidx];
    size_t o = ((size_t)bk * DHEAD + d) * KVSEQ + n;
    __nv_bfloat16 hi = __float2bfloat16(v);
    g_vthi[o] = hi;
    g_vtlo[o] = __float2bfloat16(v - __bfloat162float(hi));
}

// ---------------- host launch --------------------------------------------------
extern "C" void kernel_launch(void* const* d_in, const int* in_sizes, int n_in,
                              void* d_out, int out_size)
{
    (void)in_sizes; (void)n_in; (void)out_size;
    const float* hs  = (const float*)d_in[0];
    const float* qw  = (const float*)d_in[1];
    const float* qb  = (const float*)d_in[2];
    const float* kw  = (const float*)d_in[3];
    const float* kb  = (const float*)d_in[4];
    const float* vw  = (const float*)d_in[5];
    const float* vb  = (const float*)d_in[6];
    const float* ow  = (const float*)d_in[7];
    const int*   kqt = (const int*)  d_in[8];
    const float* kst = (const float*)d_in[9];
    const float* kmt = (const float*)d_in[10];
    const float* kfp = (const float*)d_in[11];
    const int*   vq  = (const int*)  d_in[12];
    const float* vs  = (const float*)d_in[13];
    const float* vm  = (const float*)d_in[14];
    const float* vfp = (const float*)d_in[15];
    float* out = (float*)d_out;

    __nv_bfloat16 *hshi, *hslo, *qwhi, *qwlo, *kwhi, *kwlo, *vwhi, *vwlo;
    __nv_bfloat16 *owhi, *owlo, *aohi, *aolo;
    cudaGetSymbolAddress((void**)&hshi, g_hshi);
    cudaGetSymbolAddress((void**)&hslo, g_hslo);
    cudaGetSymbolAddress((void**)&qwhi, g_qwhi);
    cudaGetSymbolAddress((void**)&qwlo, g_qwlo);
    cudaGetSymbolAddress((void**)&kwhi, g_kwhi);
    cudaGetSymbolAddress((void**)&kwlo, g_kwlo);
    cudaGetSymbolAddress((void**)&vwhi, g_vwhi);
    cudaGetSymbolAddress((void**)&vwlo, g_vwlo);
    cudaGetSymbolAddress((void**)&owhi, g_owhi);
    cudaGetSymbolAddress((void**)&owlo, g_owlo);
    cudaGetSymbolAddress((void**)&aohi, g_aohi);
    cudaGetSymbolAddress((void**)&aolo, g_aolo);

    cudaFuncSetAttribute(proj_qkv,    cudaFuncAttributeMaxDynamicSharedMemorySize, S_GEMM);
    cudaFuncSetAttribute(gemm_single, cudaFuncAttributeMaxDynamicSharedMemorySize, S_GEMM);
    cudaFuncSetAttribute(flash_attn,  cudaFuncAttributeMaxDynamicSharedMemorySize, S_FLASH);

    dim3 blk(256);

    // operand pre-split
    split_f32<<<(TOK * HDIM) / 1024, blk>>>(hs, hshi, hslo);
    split_f32<<<(HDIM * HDIM) / 1024, blk>>>(qw, qwhi, qwlo);
    split_f32<<<(KVDIM * HDIM) / 1024, blk>>>(kw, kwhi, kwlo);
    split_f32<<<(KVDIM * HDIM) / 1024, blk>>>(vw, vwhi, vwlo);
    split_f32<<<(HDIM * HDIM) / 1024, blk>>>(ow, owhi, owlo);

    // merged QKV projections (96 CTAs, 256-row tiles, single wave)
    proj_qkv<<<dim3(48, 2), blk, S_GEMM>>>(qb, kb, vb);

    // RoPE + cache assembly
    rope_q_kernel<<<(TOK * HDIM) / 256, blk>>>();
    rope_kv_kernel<<<(TOK * KVDIM) / 256, blk>>>();
    past_copy_kernel<<<dim3((32 * RESLEN * DHEAD) / 256, 2), blk>>>(kfp, vfp);
    dequant_k_kernel<<<(32 * NQK * DHEAD) / 256, blk>>>(kqt, kst, kmt);
    dequant_v_kernel<<<(32 * NQK * DHEAD) / 256, blk>>>(vq, vs, vm);

    // fused attention (3-stage pipeline)
    flash_attn<<<BATCH * NHEAD, blk, S_FLASH>>>();

    // output projection (256-row tiles)
    gemm_single<<<dim3(32, 2), blk, S_GEMM>>>(aohi, aolo, owhi, owlo, nullptr, out, HDIM, HDIM, HDIM, HDIM);
}

// round 11
// speedup vs baseline: 1.1018x; 1.1018x over previous
#include <cuda_runtime.h>
#include <cuda_bf16.h>
#include <math.h>
#include <float.h>
#include <stdint.h>

// ---------------- problem constants ----------------
#define BATCH   4
#define QLEN    128
#define HDIM    4096
#define NHEAD   32
#define NKVH    8
#define DHEAD   128
#define KVDIM   1024
#define TOK     512
#define NQK     4096
#define RESLEN  128
#define KVSEQ   4352
#define PASTLEN 4224
#define NBLK    68
#define NEGF    (-3.402823466e38f)

// ---------------- scratch ----------------
__device__ float g_qlin[TOK * HDIM];
__device__ float g_klin[TOK * KVDIM];
__device__ float g_vlin[TOK * KVDIM];
__device__ float g_q   [BATCH * NHEAD * QLEN * DHEAD];

__device__ __nv_bfloat16 g_hshi[TOK * HDIM],  g_hslo[TOK * HDIM];
__device__ __nv_bfloat16 g_qwhi[HDIM * HDIM], g_qwlo[HDIM * HDIM];
__device__ __nv_bfloat16 g_kwhi[KVDIM * HDIM], g_kwlo[KVDIM * HDIM];
__device__ __nv_bfloat16 g_vwhi[KVDIM * HDIM], g_vwlo[KVDIM * HDIM];
__device__ __nv_bfloat16 g_owhi[HDIM * HDIM], g_owlo[HDIM * HDIM];
__device__ __nv_bfloat16 g_khi [BATCH * NKVH * KVSEQ * DHEAD];
__device__ __nv_bfloat16 g_klo [BATCH * NKVH * KVSEQ * DHEAD];
__device__ __nv_bfloat16 g_vthi[BATCH * NKVH * DHEAD * KVSEQ];
__device__ __nv_bfloat16 g_vtlo[BATCH * NKVH * DHEAD * KVSEQ];
__device__ __nv_bfloat16 g_aohi[TOK * HDIM],  g_aolo[TOK * HDIM];

// ---------------- helpers ----------------
__device__ __forceinline__ void mma16816(float* c, const uint32_t* a, const uint32_t* b) {
    asm volatile(
        "mma.sync.aligned.m16n8k16.row.col.f32.bf16.bf16.f32 "
        "{%0,%1,%2,%3}, {%4,%5,%6,%7}, {%8,%9}, {%0,%1,%2,%3};"
        : "+f"(c[0]), "+f"(c[1]), "+f"(c[2]), "+f"(c[3])
        : "r"(a[0]), "r"(a[1]), "r"(a[2]), "r"(a[3]), "r"(b[0]), "r"(b[1]));
}
__device__ __forceinline__ uint32_t packb(__nv_bfloat16 a, __nv_bfloat16 b) {
    __nv_bfloat162 p(a, b);
    return *(uint32_t*)&p;
}
__device__ __forceinline__ void split2(float x0, float x1, uint32_t& hi, uint32_t& lo) {
    __nv_bfloat16 h0 = __float2bfloat16(x0), h1 = __float2bfloat16(x1);
    hi = packb(h0, h1);
    lo = packb(__float2bfloat16(x0 - __bfloat162float(h0)),
               __float2bfloat16(x1 - __bfloat162float(h1)));
}
__device__ __forceinline__ void cp16(void* s, const void* g) {
    uint32_t sa = (uint32_t)__cvta_generic_to_shared(s);
    asm volatile("cp.async.cg.shared.global [%0], [%1], 16;" :: "r"(sa), "l"(g));
}

// ---------------- fp32 -> bf16 hi/lo splitter ---------------------------------
__global__ __launch_bounds__(256) void split_f32(
    const float* __restrict__ in, __nv_bfloat16* __restrict__ hi,
    __nv_bfloat16* __restrict__ lo)
{
    int i = (blockIdx.x * 256 + threadIdx.x) * 4;
    float4 v = *(const float4*)(in + i);
    uint32_t h0, l0, h1, l1;
    split2(v.x, v.y, h0, l0);
    split2(v.z, v.w, h1, l1);
    uint2 H; H.x = h0; H.y = h1;
    uint2 L; L.x = l0; L.y = l1;
    *(uint2*)(hi + i) = H;
    *(uint2*)(lo + i) = L;
}

// ---------------- pipelined GEMM core, 128x128 C tile (R9-proven) -------------
#define PITCH 72
#define TILE_ELEMS (128 * PITCH)
#define BUF_ELEMS (4 * TILE_ELEMS)
#define S_GEMM (2 * BUF_ELEMS * 2)    // 147456 B

__device__ __forceinline__ void gemm_core(
    const __nv_bfloat16* __restrict__ Ahi, const __nv_bfloat16* __restrict__ Alo,
    const __nv_bfloat16* __restrict__ Bhi, const __nv_bfloat16* __restrict__ Blo,
    const float* __restrict__ bias, float* __restrict__ C,
    int lda, int ldb, int ldc, int K, __nv_bfloat16* sm)
{
    const int tid  = threadIdx.x;
    const int lane = tid & 31;
    const int wid  = tid >> 5;
    const int wm   = wid >> 2;
    const int wn   = wid & 3;

    float acc[4][4][4];
#pragma unroll
    for (int mt = 0; mt < 4; mt++)
#pragma unroll
        for (int nt = 0; nt < 4; nt++)
#pragma unroll
            for (int i = 0; i < 4; i++) acc[mt][nt][i] = 0.f;

    const int nch = K >> 6;

#define G_STAGE(ch, buf) do {                                              \
    __nv_bfloat16* d0 = sm + (buf) * BUF_ELEMS;                            \
    __nv_bfloat16* d1 = d0 + TILE_ELEMS;                                   \
    __nv_bfloat16* d2 = d0 + 2 * TILE_ELEMS;                               \
    __nv_bfloat16* d3 = d0 + 3 * TILE_ELEMS;                               \
    const int k0 = (ch) << 6;                                              \
    _Pragma("unroll")                                                      \
    for (int i = 0; i < 4; i++) {                                          \
        int u = i * 256 + tid;                                             \
        int r = u >> 3, kp = (u & 7) * 8, so = r * PITCH + kp;             \
        cp16(d0 + so, Ahi + (size_t)r * lda + k0 + kp);                    \
        cp16(d1 + so, Alo + (size_t)r * lda + k0 + kp);                    \
        cp16(d2 + so, Bhi + (size_t)r * ldb + k0 + kp);                    \
        cp16(d3 + so, Blo + (size_t)r * ldb + k0 + kp);                    \
    }                                                                      \
    asm volatile("cp.async.commit_group;");                                \
} while (0)

    G_STAGE(0, 0);
    for (int ch = 0; ch < nch; ch++) {
        if (ch + 1 < nch) {
            G_STAGE(ch + 1, (ch + 1) & 1);
            asm volatile("cp.async.wait_group 1;");
        } else {
            asm volatile("cp.async.wait_group 0;");
        }
        __syncthreads();

        const __nv_bfloat16* sAhi = sm + (ch & 1) * BUF_ELEMS;
        const __nv_bfloat16* sAlo = sAhi + TILE_ELEMS;
        const __nv_bfloat16* sBhi = sAhi + 2 * TILE_ELEMS;
        const __nv_bfloat16* sBlo = sAhi + 3 * TILE_ELEMS;

#pragma unroll
        for (int ks = 0; ks < 4; ks++) {
            const int kb = ks * 16 + (lane & 3) * 2;
            uint32_t bh[4][2], bl[4][2];
            const int nrow = wn * 32 + (lane >> 2);
#pragma unroll
            for (int nt = 0; nt < 4; nt++) {
                int nb = (nrow + nt * 8) * PITCH + kb;
                bh[nt][0] = *(uint32_t*)&sBhi[nb];
                bh[nt][1] = *(uint32_t*)&sBhi[nb + 8];
                bl[nt][0] = *(uint32_t*)&sBlo[nb];
                bl[nt][1] = *(uint32_t*)&sBlo[nb + 8];
            }
            const int arow = wm * 64 + (lane >> 2);
#pragma unroll
            for (int mt = 0; mt < 4; mt++) {
                int ab = (arow + mt * 16) * PITCH + kb;
                uint32_t ah[4], al[4];
                ah[0] = *(uint32_t*)&sAhi[ab];
                ah[1] = *(uint32_t*)&sAhi[ab + 8 * PITCH];
                ah[2] = *(uint32_t*)&sAhi[ab + 8];
                ah[3] = *(uint32_t*)&sAhi[ab + 8 * PITCH + 8];
                al[0] = *(uint32_t*)&sAlo[ab];
                al[1] = *(uint32_t*)&sAlo[ab + 8 * PITCH];
                al[2] = *(uint32_t*)&sAlo[ab + 8];
                al[3] = *(uint32_t*)&sAlo[ab + 8 * PITCH + 8];
#pragma unroll
                for (int nt = 0; nt < 4; nt++) {
                    mma16816(acc[mt][nt], ah, bh[nt]);
                    mma16816(acc[mt][nt], ah, bl[nt]);
                    mma16816(acc[mt][nt], al, bh[nt]);
                }
            }
        }
        __syncthreads();
    }
#undef G_STAGE

    const int r0 = wm * 64 + (lane >> 2);
    const int c0 = wn * 32 + (lane & 3) * 2;
#pragma unroll
    for (int mt = 0; mt < 4; mt++) {
#pragma unroll
        for (int nt = 0; nt < 4; nt++) {
            int cc = c0 + nt * 8;
#pragma unroll
            for (int half = 0; half < 2; half++) {
                int r = r0 + mt * 16 + half * 8;
                float2 o;
                o.x = acc[mt][nt][half * 2 + 0];
                o.y = acc[mt][nt][half * 2 + 1];
                if (bias) {
                    o.x += bias[cc];
                    o.y += bias[cc + 1];
                }
                *(float2*)(C + (size_t)r * ldc + cc) = o;
            }
        }
    }
}

// ---------------- merged QKV projection (192 CTAs) ----------------------------
__global__ __launch_bounds__(256) void proj_qkv(
    const float* __restrict__ qb, const float* __restrict__ kb,
    const float* __restrict__ vb)
{
    extern __shared__ __nv_bfloat16 sm[];
    const int x = blockIdx.x;          // 0..47
    const int y = blockIdx.y;          // 0..3
    const __nv_bfloat16 *Bh, *Bl;
    const float* bias;
    float* C;
    int N, tx;
    if (x < 32)      { tx = x;      Bh = g_qwhi; Bl = g_qwlo; bias = qb; C = g_qlin; N = HDIM; }
    else if (x < 40) { tx = x - 32; Bh = g_kwhi; Bl = g_kwlo; bias = kb; C = g_klin; N = KVDIM; }
    else             { tx = x - 40; Bh = g_vwhi; Bl = g_vwlo; bias = vb; C = g_vlin; N = KVDIM; }

    const size_t arow0 = (size_t)y * 128;
    const size_t brow0 = (size_t)tx * 128;
    gemm_core(g_hshi + arow0 * HDIM, g_hslo + arow0 * HDIM,
              Bh + brow0 * HDIM, Bl + brow0 * HDIM,
              bias + brow0, C + arow0 * N + brow0,
              HDIM, HDIM, N, HDIM, sm);
}

// ---------------- O projection ------------------------------------------------
__global__ __launch_bounds__(256) void gemm_single(
    const __nv_bfloat16* __restrict__ Ahi, const __nv_bfloat16* __restrict__ Alo,
    const __nv_bfloat16* __restrict__ Bhi, const __nv_bfloat16* __restrict__ Blo,
    const float* __restrict__ bias, float* __restrict__ C,
    int lda, int ldb, int ldc, int K)
{
    extern __shared__ __nv_bfloat16 sm[];
    const size_t arow0 = (size_t)(blockIdx.y * 128);
    const size_t brow0 = (size_t)(blockIdx.x * 128);
    gemm_core(Ahi + arow0 * lda, Alo + arow0 * lda,
              Bhi + brow0 * ldb, Blo + brow0 * ldb,
              bias ? bias + brow0 : nullptr, C + arow0 * ldc + brow0,
              lda, ldb, ldc, K, sm);
}

// ---------------- fused flash attention (2-stage, R9-proven) ------------------
#define FK_PITCH 136
#define FV_PITCH 72
#define FBUF_ELEMS (2 * 64 * FK_PITCH + 2 * 128 * FV_PITCH)   // 35840 elems
#define S_FLASH (2 * FBUF_ELEMS * 2)                          // 143360 B

__global__ __launch_bounds__(256, 1) void flash_attn()
{
    extern __shared__ __nv_bfloat16 fsm[];

    const int bh = blockIdx.x;
    const int b = bh >> 5, h = bh & 31, kvh = h >> 2;
    const int bk = b * NKVH + kvh;
    const int tid = threadIdx.x, lane = tid & 31, w = tid >> 5;
    const int rq = w * 16 + (lane >> 2);
    const int q2 = (lane & 3) * 2;
    const float isq = 0.08838834764831845f;

    const float* Q = g_q + (size_t)bh * QLEN * DHEAD;
    uint32_t qhi[8][4], qlo[8][4];
#pragma unroll
    for (int kk = 0; kk < 8; kk++) {
#pragma unroll
        for (int f = 0; f < 4; f++) {
            int rr = rq + ((f & 1) ? 8 : 0);
            int kc = kk * 16 + ((f & 2) ? 8 : 0) + q2;
            split2(Q[rr * DHEAD + kc], Q[rr * DHEAD + kc + 1], qhi[kk][f], qlo[kk][f]);
        }
    }

    const __nv_bfloat16* Khi = g_khi + (size_t)bk * KVSEQ * DHEAD;
    const __nv_bfloat16* Klo = g_klo + (size_t)bk * KVSEQ * DHEAD;
    const __nv_bfloat16* Vhi = g_vthi + (size_t)bk * DHEAD * KVSEQ;
    const __nv_bfloat16* Vlo = g_vtlo + (size_t)bk * DHEAD * KVSEQ;

    float m0 = NEGF, m1 = NEGF, l0 = 0.f, l1 = 0.f;
    float oacc[16][4];
#pragma unroll
    for (int td = 0; td < 16; td++)
#pragma unroll
        for (int i = 0; i < 4; i++) oacc[td][i] = 0.f;

#define F_STAGE(j, buf) do {                                               \
    __nv_bfloat16* dKhi = fsm + (buf) * FBUF_ELEMS;                        \
    __nv_bfloat16* dKlo = dKhi + 64 * FK_PITCH;                            \
    __nv_bfloat16* dVhi = dKhi + 2 * 64 * FK_PITCH;                        \
    __nv_bfloat16* dVlo = dVhi + 128 * FV_PITCH;                           \
    _Pragma("unroll")                                                      \
    for (int i = 0; i < 4; i++) {                                          \
        int u = i * 256 + tid;                                             \
        int n = u >> 4, kp = (u & 15) * 8;                                 \
        size_t go = (size_t)((j) * 64 + n) * DHEAD + kp;                   \
        cp16(dKhi + n * FK_PITCH + kp, Khi + go);                          \
        cp16(dKlo + n * FK_PITCH + kp, Klo + go);                          \
        int d = u >> 3, vp = (u & 7) * 8;                                  \
        size_t gv = (size_t)d * KVSEQ + (j) * 64 + vp;                     \
        cp16(dVhi + d * FV_PITCH + vp, Vhi + gv);                          \
        cp16(dVlo + d * FV_PITCH + vp, Vlo + gv);                          \
    }                                                                      \
    asm volatile("cp.async.commit_group;");                                \
} while (0)

    F_STAGE(0, 0);
    for (int j = 0; j < NBLK; j++) {
        if (j + 1 < NBLK) {
            F_STAGE(j + 1, (j + 1) & 1);
            asm volatile("cp.async.wait_group 1;");
        } else {
            asm volatile("cp.async.wait_group 0;");
        }
        __syncthreads();

        const __nv_bfloat16* sKhi = fsm + (j & 1) * FBUF_ELEMS;
        const __nv_bfloat16* sKlo = sKhi + 64 * FK_PITCH;
        const __nv_bfloat16* sVhi = sKhi + 2 * 64 * FK_PITCH;
        const __nv_bfloat16* sVlo = sVhi + 128 * FV_PITCH;

        float sacc[8][4];
#pragma unroll
        for (int nt = 0; nt < 8; nt++)
#pragma unroll
            for (int i = 0; i < 4; i++) sacc[nt][i] = 0.f;

#pragma unroll
        for (int kk = 0; kk < 8; kk++) {
            const int kb = kk * 16 + q2;
#pragma unroll
            for (int nt = 0; nt < 8; nt++) {
                int nb = (nt * 8 + (lane >> 2)) * FK_PITCH + kb;
                uint32_t bhf[2], blf[2];
                bhf[0] = *(uint32_t*)&sKhi[nb];
                bhf[1] = *(uint32_t*)&sKhi[nb + 8];
                blf[0] = *(uint32_t*)&sKlo[nb];
                blf[1] = *(uint32_t*)&sKlo[nb + 8];
                mma16816(sacc[nt], qhi[kk], bhf);
                mma16816(sacc[nt], qhi[kk], blf);
                mma16816(sacc[nt], qlo[kk], bhf);
            }
        }

#pragma unroll
        for (int nt = 0; nt < 8; nt++)
#pragma unroll
            for (int i = 0; i < 4; i++) sacc[nt][i] *= isq;
        if (j >= 66) {
            int jc = j * 64 - PASTLEN;
#pragma unroll
            for (int nt = 0; nt < 8; nt++) {
                int c = jc + nt * 8 + q2;
                if (c     > rq)     sacc[nt][0] = NEGF;
                if (c + 1 > rq)     sacc[nt][1] = NEGF;
                if (c     > rq + 8) sacc[nt][2] = NEGF;
                if (c + 1 > rq + 8) sacc[nt][3] = NEGF;
            }
        }

        float mx0 = NEGF, mx1 = NEGF;
#pragma unroll
        for (int nt = 0; nt < 8; nt++) {
            mx0 = fmaxf(mx0, fmaxf(sacc[nt][0], sacc[nt][1]));
            mx1 = fmaxf(mx1, fmaxf(sacc[nt][2], sacc[nt][3]));
        }
        mx0 = fmaxf(mx0, __shfl_xor_sync(0xffffffffu, mx0, 1));
        mx0 = fmaxf(mx0, __shfl_xor_sync(0xffffffffu, mx0, 2));
        mx1 = fmaxf(mx1, __shfl_xor_sync(0xffffffffu, mx1, 1));
        mx1 = fmaxf(mx1, __shfl_xor_sync(0xffffffffu, mx1, 2));

        float mn0 = fmaxf(m0, mx0), mn1 = fmaxf(m1, mx1);
        float a0 = __expf(m0 - mn0), a1 = __expf(m1 - mn1);

        float rs0 = 0.f, rs1 = 0.f;
#pragma unroll
        for (int nt = 0; nt < 8; nt++) {
            sacc[nt][0] = __expf(sacc[nt][0] - mn0);
            sacc[nt][1] = __expf(sacc[nt][1] - mn0);
            sacc[nt][2] = __expf(sacc[nt][2] - mn1);
            sacc[nt][3] = __expf(sacc[nt][3] - mn1);
            rs0 += sacc[nt][0] + sacc[nt][1];
            rs1 += sacc[nt][2] + sacc[nt][3];
        }
        rs0 += __shfl_xor_sync(0xffffffffu, rs0, 1);
        rs0 += __shfl_xor_sync(0xffffffffu, rs0, 2);
        rs1 += __shfl_xor_sync(0xffffffffu, rs1, 1);
        rs1 += __shfl_xor_sync(0xffffffffu, rs1, 2);
        l0 = l0 * a0 + rs0;
        l1 = l1 * a1 + rs1;
        m0 = mn0; m1 = mn1;

#pragma unroll
        for (int td = 0; td < 16; td++) {
            oacc[td][0] *= a0; oacc[td][1] *= a0;
            oacc[td][2] *= a1; oacc[td][3] *= a1;
        }

#pragma unroll
        for (int kk2 = 0; kk2 < 4; kk2++) {
            uint32_t phi[4], plo[4];
            split2(sacc[2 * kk2][0],     sacc[2 * kk2][1],     phi[0], plo[0]);
            split2(sacc[2 * kk2][2],     sacc[2 * kk2][3],     phi[1], plo[1]);
            split2(sacc[2 * kk2 + 1][0], sacc[2 * kk2 + 1][1], phi[2], plo[2]);
            split2(sacc[2 * kk2 + 1][2], sacc[2 * kk2 + 1][3], phi[3], plo[3]);
            const int kb = kk2 * 16 + q2;
#pragma unroll
            for (int td = 0; td < 16; td++) {
                int vb = (td * 8 + (lane >> 2)) * FV_PITCH + kb;
                uint32_t vbh[2], vbl[2];
                vbh[0] = *(uint32_t*)&sVhi[vb];
                vbh[1] = *(uint32_t*)&sVhi[vb + 8];
                vbl[0] = *(uint32_t*)&sVlo[vb];
                vbl[1] = *(uint32_t*)&sVlo[vb + 8];
                mma16816(oacc[td], phi, vbh);
                mma16816(oacc[td], phi, vbl);
                mma16816(oacc[td], plo, vbh);
            }
        }
        __syncthreads();
    }
#undef F_STAGE

    float inv0 = 1.f / l0, inv1 = 1.f / l1;
#pragma unroll
    for (int td = 0; td < 16; td++) {
        int cd = h * DHEAD + td * 8 + q2;
        {
            float x0 = oacc[td][0] * inv0, x1 = oacc[td][1] * inv0;
            uint32_t hi, lo;
            split2(x0, x1, hi, lo);
            size_t o = (size_t)(b * QLEN + rq) * HDIM + cd;
            *(uint32_t*)&g_aohi[o] = hi;
            *(uint32_t*)&g_aolo[o] = lo;
        }
        {
            float x0 = oacc[td][2] * inv1, x1 = oacc[td][3] * inv1;
            uint32_t hi, lo;
            split2(x0, x1, hi, lo);
            size_t o = (size_t)(b * QLEN + rq + 8) * HDIM + cd;
            *(uint32_t*)&g_aohi[o] = hi;
            *(uint32_t*)&g_aolo[o] = lo;
        }
    }
}

// ---------------- RoPE Q ------------------------------------------------------
__global__ __launch_bounds__(256) void rope_q_kernel()
{
    int idx = blockIdx.x * 256 + threadIdx.x;
    int d = idx & 127;
    int t = (idx >> 7) & 127;
    int h = (idx >> 14) & 31;
    int b = idx >> 19;
    size_t base = ((size_t)(b * QLEN + t)) * HDIM + (size_t)h * DHEAD;
    int i = d & 63;
    float inv = 1.0f / powf(1.0e6f, (float)(2 * i) / 128.0f);
    float ang = (float)(PASTLEN + t) * inv;
    float s, c;
    sincosf(ang, &s, &c);
    float x  = g_qlin[base + d];
    float xo = g_qlin[base + ((d < 64) ? d + 64 : d - 64)];
    g_q[idx] = (d < 64) ? (x * c - xo * s) : (x * c + xo * s);
}

// ---------------- merged RoPE-K + V-scatter (new tokens) ----------------------
__global__ __launch_bounds__(256) void rope_kv_kernel()
{
    int idx = blockIdx.x * 256 + threadIdx.x;      // 4*8*128*128
    {
        int d   = idx & 127;
        int t   = (idx >> 7) & 127;
        int kvh = (idx >> 14) & 7;
        int b   = idx >> 17;
        size_t base = ((size_t)(b * QLEN + t)) * KVDIM + (size_t)kvh * DHEAD;
        int i = d & 63;
        float inv = 1.0f / powf(1.0e6f, (float)(2 * i) / 128.0f);
        float ang = (float)(PASTLEN + t) * inv;
        float s, c;
        sincosf(ang, &s, &c);
        float x  = g_klin[base + d];
        float xo = g_klin[base + ((d < 64) ? d + 64 : d - 64)];
        float v  = (d < 64) ? (x * c - xo * s) : (x * c + xo * s);
        size_t o = (((size_t)(b * NKVH + kvh)) * KVSEQ + PASTLEN + t) * DHEAD + d;
        __nv_bfloat16 hi = __float2bfloat16(v);
        g_khi[o] = hi;
        g_klo[o] = __float2bfloat16(v - __bfloat162float(hi));
    }
    {
        int t   = idx & 127;
        int d   = (idx >> 7) & 127;
        int kvh = (idx >> 14) & 7;
        int b   = idx >> 17;
        float v = g_vlin[((size_t)(b * QLEN + t)) * KVDIM + kvh * DHEAD + d];
        size_t o = ((size_t)(b * NKVH + kvh) * DHEAD + d) * KVSEQ + PASTLEN + t;
        __nv_bfloat16 hi = __float2bfloat16(v);
        g_vthi[o] = hi;
        g_vtlo[o] = __float2bfloat16(v - __bfloat162float(hi));
    }
}

// ---------------- fp32 past copy (split) --------------------------------------
__global__ __launch_bounds__(256) void past_copy_kernel(
    const float* __restrict__ kfp, const float* __restrict__ vfp)
{
    int idx = blockIdx.x * 256 + threadIdx.x;      // 32*128*128
    int d  = idx & 127;
    int r  = (idx >> 7) & 127;
    int bk = idx >> 14;
    size_t src = ((size_t)bk * RESLEN + r) * DHEAD + d;
    if (blockIdx.y == 0) {
        float v = kfp[src];
        size_t o = ((size_t)bk * KVSEQ + NQK + r) * DHEAD + d;
        __nv_bfloat16 hi = __float2bfloat16(v);
        g_khi[o] = hi;
        g_klo[o] = __float2bfloat16(v - __bfloat162float(hi));
    } else {
        float v = vfp[src];
        size_t o = ((size_t)bk * DHEAD + d) * KVSEQ + NQK + r;
        __nv_bfloat16 hi = __float2bfloat16(v);
        g_vthi[o] = hi;
        g_vtlo[o] = __float2bfloat16(v - __bfloat162float(hi));
    }
}

// ---------------- dequant 2-bit K -> split K cache ----------------------------
__global__ __launch_bounds__(256) void dequant_k_kernel(
    const int* __restrict__ kq, const float* __restrict__ ks,
    const float* __restrict__ km)
{
    int idx = blockIdx.x * 256 + threadIdx.x;
    int d  = idx & 127;
    int n  = (idx >> 7) & 4095;
    int bk = idx >> 19;
    unsigned word = (unsigned)kq[((size_t)bk * DHEAD + d) * (NQK / 16) + (n >> 4)];
    float code = (float)((word >> ((n & 15) * 2)) & 3u);
    size_t sidx = ((size_t)bk * DHEAD + d) * (NQK / 64) + (n >> 6);
    float v = code * ks[sidx] + km[sidx];
    size_t o = ((size_t)bk * KVSEQ + n) * DHEAD + d;
    __nv_bfloat16 hi = __float2bfloat16(v);
    g_khi[o] = hi;
    g_klo[o] = __float2bfloat16(v - __bfloat162float(hi));
}

// ---------------- dequant 2-bit V -> split V^T cache --------------------------
__global__ __launch_bounds__(256) void dequant_v_kernel(
    const int* __restrict__ vq, const float* __restrict__ vs,
    const float* __restrict__ vm)
{
    int idx = blockIdx.x * 256 + threadIdx.x;
    int n  = idx & 4095;
    int d  = (idx >> 12) & 127;
    int bk = idx >> 19;
    unsigned word = (unsigned)vq[((size_t)bk * NQK + n) * (DHEAD / 16) + (d >> 4)];
    float code = (float)((word >> ((d & 15) * 2)) & 3u);
    size_t sidx = ((size_t)bk * NQK + n) * (DHEAD / 64) + (d >> 6);
    float v = code * vs[sidx] + vm[sidx];
    size_t o = ((size_t)bk * DHEAD + d) * KVSEQ + n;
    __nv_bfloat16 hi = __float2bfloat16(v);
    g_vthi[o] = hi;
    g_vtlo[o] = __float2bfloat16(v - __bfloat162float(hi));
}

// ---------------- host launch --------------------------------------------------
extern "C" void kernel_launch(void* const* d_in, const int* in_sizes, int n_in,
                              void* d_out, int out_size)
{
    (void)in_sizes; (void)n_in; (void)out_size;
    const float* hs  = (const float*)d_in[0];
    const float* qw  = (const float*)d_in[1];
    const float* qb  = (const float*)d_in[2];
    const float* kw  = (const float*)d_in[3];
    const float* kb  = (const float*)d_in[4];
    const float* vw  = (const float*)d_in[5];
    const float* vb  = (const float*)d_in[6];
    const float* ow  = (const float*)d_in[7];
    const int*   kqt = (const int*)  d_in[8];
    const float* kst = (const float*)d_in[9];
    const float* kmt = (const float*)d_in[10];
    const float* kfp = (const float*)d_in[11];
    const int*   vq  = (const int*)  d_in[12];
    const float* vs  = (const float*)d_in[13];
    const float* vm  = (const float*)d_in[14];
    const float* vfp = (const float*)d_in[15];
    float* out = (float*)d_out;

    __nv_bfloat16 *hshi, *hslo, *qwhi, *qwlo, *kwhi, *kwlo, *vwhi, *vwlo;
    __nv_bfloat16 *owhi, *owlo, *aohi, *aolo;
    cudaGetSymbolAddress((void**)&hshi, g_hshi);
    cudaGetSymbolAddress((void**)&hslo, g_hslo);
    cudaGetSymbolAddress((void**)&qwhi, g_qwhi);
    cudaGetSymbolAddress((void**)&qwlo, g_qwlo);
    cudaGetSymbolAddress((void**)&kwhi, g_kwhi);
    cudaGetSymbolAddress((void**)&kwlo, g_kwlo);
    cudaGetSymbolAddress((void**)&vwhi, g_vwhi);
    cudaGetSymbolAddress((void**)&vwlo, g_vwlo);
    cudaGetSymbolAddress((void**)&owhi, g_owhi);
    cudaGetSymbolAddress((void**)&owlo, g_owlo);
    cudaGetSymbolAddress((void**)&aohi, g_aohi);
    cudaGetSymbolAddress((void**)&aolo, g_aolo);

    cudaFuncSetAttribute(proj_qkv,    cudaFuncAttributeMaxDynamicSharedMemorySize, S_GEMM);
    cudaFuncSetAttribute(gemm_single, cudaFuncAttributeMaxDynamicSharedMemorySize, S_GEMM);
    cudaFuncSetAttribute(flash_attn,  cudaFuncAttributeMaxDynamicSharedMemorySize, S_FLASH);

    // lazy-init side stream + fork/join events (deterministic; created once)
    static cudaStream_t sB = nullptr;
    static cudaEvent_t evFork = nullptr, evJoin = nullptr;
    if (sB == nullptr) {
        cudaStreamCreateWithFlags(&sB, cudaStreamNonBlocking);
        cudaEventCreateWithFlags(&evFork, cudaEventDisableTiming);
        cudaEventCreateWithFlags(&evJoin, cudaEventDisableTiming);
    }

    dim3 blk(256);

    // fork: input-only work onto side stream (dequants + past copy + ow split)
    cudaEventRecord(evFork, 0);
    cudaStreamWaitEvent(sB, evFork, 0);
    dequant_k_kernel<<<(32 * NQK * DHEAD) / 256, blk, 0, sB>>>(kqt, kst, kmt);
    dequant_v_kernel<<<(32 * NQK * DHEAD) / 256, blk, 0, sB>>>(vq, vs, vm);
    past_copy_kernel<<<dim3((32 * RESLEN * DHEAD) / 256, 2), blk, 0, sB>>>(kfp, vfp);
    split_f32<<<(HDIM * HDIM) / 1024, blk, 0, sB>>>(ow, owhi, owlo);
    cudaEventRecord(evJoin, sB);

    // main stream: proj-chain splits
    split_f32<<<(TOK * HDIM) / 1024, blk>>>(hs, hshi, hslo);
    split_f32<<<(HDIM * HDIM) / 1024, blk>>>(qw, qwhi, qwlo);
    split_f32<<<(KVDIM * HDIM) / 1024, blk>>>(kw, kwhi, kwlo);
    split_f32<<<(KVDIM * HDIM) / 1024, blk>>>(vw, vwhi, vwlo);

    // merged QKV projections (192 CTAs)
    proj_qkv<<<dim3(48, 4), blk, S_GEMM>>>(qb, kb, vb);

    // RoPE
    rope_q_kernel<<<(TOK * HDIM) / 256, blk>>>();
    rope_kv_kernel<<<(TOK * KVDIM) / 256, blk>>>();

    // join: flash needs side-stream results (dequants/past); O-proj needs ow split
    cudaStreamWaitEvent(0, evJoin, 0);

    // fused attention
    flash_attn<<<BATCH * NHEAD, blk, S_FLASH>>>();

    // output projection
    gemm_single<<<dim3(32, 4), blk, S_GEMM>>>(aohi, aolo, owhi, owlo, nullptr, out, HDIM, HDIM, HDIM, HDIM);
}

// round 14
// speedup vs baseline: 1.1252x; 1.0212x over previous
#include <cuda_runtime.h>
#include <cuda_bf16.h>
#include <math.h>
#include <float.h>
#include <stdint.h>

// ---------------- problem constants ----------------
#define BATCH   4
#define QLEN    128
#define HDIM    4096
#define NHEAD   32
#define NKVH    8
#define DHEAD   128
#define KVDIM   1024
#define TOK     512
#define NQK     4096
#define RESLEN  128
#define KVSEQ   4352
#define PASTLEN 4224
#define NBLK    68
#define NEGF    (-3.402823466e38f)

// ---------------- scratch ----------------
__device__ float g_qlin[TOK * HDIM];
__device__ float g_klin[TOK * KVDIM];
__device__ float g_vlin[TOK * KVDIM];
__device__ float g_q   [BATCH * NHEAD * QLEN * DHEAD];

__device__ __nv_bfloat16 g_hshi[TOK * HDIM],  g_hslo[TOK * HDIM];
__device__ __nv_bfloat16 g_qwhi[HDIM * HDIM], g_qwlo[HDIM * HDIM];
__device__ __nv_bfloat16 g_kwhi[KVDIM * HDIM], g_kwlo[KVDIM * HDIM];
__device__ __nv_bfloat16 g_vwhi[KVDIM * HDIM], g_vwlo[KVDIM * HDIM];
__device__ __nv_bfloat16 g_owhi[HDIM * HDIM], g_owlo[HDIM * HDIM];
__device__ __nv_bfloat16 g_khi [BATCH * NKVH * KVSEQ * DHEAD];
__device__ __nv_bfloat16 g_klo [BATCH * NKVH * KVSEQ * DHEAD];
__device__ __nv_bfloat16 g_vthi[BATCH * NKVH * DHEAD * KVSEQ];
__device__ __nv_bfloat16 g_vtlo[BATCH * NKVH * DHEAD * KVSEQ];
__device__ __nv_bfloat16 g_aohi[TOK * HDIM],  g_aolo[TOK * HDIM];

// ---------------- helpers ----------------
__device__ __forceinline__ void mma16816(float* c, const uint32_t* a, const uint32_t* b) {
    asm volatile(
        "mma.sync.aligned.m16n8k16.row.col.f32.bf16.bf16.f32 "
        "{%0,%1,%2,%3}, {%4,%5,%6,%7}, {%8,%9}, {%0,%1,%2,%3};"
        : "+f"(c[0]), "+f"(c[1]), "+f"(c[2]), "+f"(c[3])
        : "r"(a[0]), "r"(a[1]), "r"(a[2]), "r"(a[3]), "r"(b[0]), "r"(b[1]));
}
__device__ __forceinline__ void ldsm4(uint32_t& r0, uint32_t& r1, uint32_t& r2,
                                      uint32_t& r3, uint32_t addr) {
    asm volatile("ldmatrix.sync.aligned.m8n8.x4.shared.b16 {%0,%1,%2,%3}, [%4];"
        : "=r"(r0), "=r"(r1), "=r"(r2), "=r"(r3) : "r"(addr));
}
__device__ __forceinline__ uint32_t smem_u32(const void* p) {
    uint32_t a;
    asm("{ .reg .u64 t; cvta.to.shared.u64 t, %1; cvt.u32.u64 %0, t; }" : "=r"(a) : "l"(p));
    return a;
}
__device__ __forceinline__ uint32_t packb(__nv_bfloat16 a, __nv_bfloat16 b) {
    __nv_bfloat162 p(a, b);
    return *(uint32_t*)&p;
}
__device__ __forceinline__ void split2(float x0, float x1, uint32_t& hi, uint32_t& lo) {
    __nv_bfloat16 h0 = __float2bfloat16(x0), h1 = __float2bfloat16(x1);
    hi = packb(h0, h1);
    lo = packb(__float2bfloat16(x0 - __bfloat162float(h0)),
               __float2bfloat16(x1 - __bfloat162float(h1)));
}
__device__ __forceinline__ void cp16(void* s, const void* g) {
    uint32_t sa = (uint32_t)__cvta_generic_to_shared(s);
    asm volatile("cp.async.cg.shared.global [%0], [%1], 16;" :: "r"(sa), "l"(g));
}

// ---------------- fp32 -> bf16 hi/lo splitter ---------------------------------
__global__ __launch_bounds__(256) void split_f32(
    const float* __restrict__ in, __nv_bfloat16* __restrict__ hi,
    __nv_bfloat16* __restrict__ lo)
{
    int i = (blockIdx.x * 256 + threadIdx.x) * 4;
    float4 v = *(const float4*)(in + i);
    uint32_t h0, l0, h1, l1;
    split2(v.x, v.y, h0, l0);
    split2(v.z, v.w, h1, l1);
    uint2 H; H.x = h0; H.y = h1;
    uint2 L; L.x = l0; L.y = l1;
    *(uint2*)(hi + i) = H;
    *(uint2*)(lo + i) = L;
}

// ---------------- pipelined GEMM core, 128x128 C tile, LDSM frags -------------
#define PITCH 72
#define TILE_ELEMS (128 * PITCH)
#define BUF_ELEMS (4 * TILE_ELEMS)
#define S_GEMM (2 * BUF_ELEMS * 2)    // 147456 B

__device__ __forceinline__ void gemm_core(
    const __nv_bfloat16* __restrict__ Ahi, const __nv_bfloat16* __restrict__ Alo,
    const __nv_bfloat16* __restrict__ Bhi, const __nv_bfloat16* __restrict__ Blo,
    const float* __restrict__ bias, float* __restrict__ C,
    int lda, int ldb, int ldc, int K, __nv_bfloat16* sm)
{
    const int tid  = threadIdx.x;
    const int lane = tid & 31;
    const int wid  = tid >> 5;
    const int wm   = wid >> 2;
    const int wn   = wid & 3;
    const int Lm   = lane >> 3;       // ldmatrix matrix id
    const int Lr   = lane & 7;        // row within matrix
    // ldmatrix per-lane element offsets (A-type / B-type frag layouts)
    const int aoff = ((Lm & 1) * 8 + Lr) * PITCH + (Lm >> 1) * 8;
    const int boff = ((Lm >> 1) * 8 + Lr) * PITCH + (Lm & 1) * 8;
    const uint32_t sm_u = smem_u32(sm);

    float acc[4][4][4];
#pragma unroll
    for (int mt = 0; mt < 4; mt++)
#pragma unroll
        for (int nt = 0; nt < 4; nt++)
#pragma unroll
            for (int i = 0; i < 4; i++) acc[mt][nt][i] = 0.f;

    const int nch = K >> 6;

#define G_STAGE(ch, buf) do {                                              \
    __nv_bfloat16* d0 = sm + (buf) * BUF_ELEMS;                            \
    __nv_bfloat16* d1 = d0 + TILE_ELEMS;                                   \
    __nv_bfloat16* d2 = d0 + 2 * TILE_ELEMS;                               \
    __nv_bfloat16* d3 = d0 + 3 * TILE_ELEMS;                               \
    const int k0 = (ch) << 6;                                              \
    _Pragma("unroll")                                                      \
    for (int i = 0; i < 4; i++) {                                          \
        int u = i * 256 + tid;                                             \
        int r = u >> 3, kp = (u & 7) * 8, so = r * PITCH + kp;             \
        cp16(d0 + so, Ahi + (size_t)r * lda + k0 + kp);                    \
        cp16(d1 + so, Alo + (size_t)r * lda + k0 + kp);                    \
        cp16(d2 + so, Bhi + (size_t)r * ldb + k0 + kp);                    \
        cp16(d3 + so, Blo + (size_t)r * ldb + k0 + kp);                    \
    }                                                                      \
    asm volatile("cp.async.commit_group;");                                \
} while (0)

    G_STAGE(0, 0);
    for (int ch = 0; ch < nch; ch++) {
        if (ch + 1 < nch) {
            G_STAGE(ch + 1, (ch + 1) & 1);
            asm volatile("cp.async.wait_group 1;");
        } else {
            asm volatile("cp.async.wait_group 0;");
        }
        __syncthreads();

        const uint32_t sAhi_u = sm_u + (uint32_t)((ch & 1) * BUF_ELEMS) * 2u;
        const uint32_t sAlo_u = sAhi_u + TILE_ELEMS * 2u;
        const uint32_t sBhi_u = sAhi_u + 2u * TILE_ELEMS * 2u;
        const uint32_t sBlo_u = sAhi_u + 3u * TILE_ELEMS * 2u;

#pragma unroll
        for (int ks = 0; ks < 4; ks++) {
            uint32_t bh[4][2], bl[4][2];
#pragma unroll
            for (int np = 0; np < 2; np++) {
                uint32_t off = (uint32_t)(((wn * 32 + np * 16) * PITCH + ks * 16 + boff) * 2);
                ldsm4(bh[2*np][0], bh[2*np][1], bh[2*np+1][0], bh[2*np+1][1], sBhi_u + off);
                ldsm4(bl[2*np][0], bl[2*np][1], bl[2*np+1][0], bl[2*np+1][1], sBlo_u + off);
            }
#pragma unroll
            for (int mt = 0; mt < 4; mt++) {
                uint32_t offA = (uint32_t)(((wm * 64 + mt * 16) * PITCH + ks * 16 + aoff) * 2);
                uint32_t ah[4], al[4];
                ldsm4(ah[0], ah[1], ah[2], ah[3], sAhi_u + offA);
                ldsm4(al[0], al[1], al[2], al[3], sAlo_u + offA);
#pragma unroll
                for (int nt = 0; nt < 4; nt++) {
                    mma16816(acc[mt][nt], ah, bh[nt]);
                    mma16816(acc[mt][nt], ah, bl[nt]);
                    mma16816(acc[mt][nt], al, bh[nt]);
                }
            }
        }
        __syncthreads();
    }
#undef G_STAGE

    const int r0 = wm * 64 + (lane >> 2);
    const int c0 = wn * 32 + (lane & 3) * 2;
#pragma unroll
    for (int mt = 0; mt < 4; mt++) {
#pragma unroll
        for (int nt = 0; nt < 4; nt++) {
            int cc = c0 + nt * 8;
#pragma unroll
            for (int half = 0; half < 2; half++) {
                int r = r0 + mt * 16 + half * 8;
                float2 o;
                o.x = acc[mt][nt][half * 2 + 0];
                o.y = acc[mt][nt][half * 2 + 1];
                if (bias) {
                    o.x += bias[cc];
                    o.y += bias[cc + 1];
                }
                *(float2*)(C + (size_t)r * ldc + cc) = o;
            }
        }
    }
}

// ---------------- merged QKV projection (192 CTAs) ----------------------------
__global__ __launch_bounds__(256) void proj_qkv(
    const float* __restrict__ qb, const float* __restrict__ kb,
    const float* __restrict__ vb)
{
    extern __shared__ __nv_bfloat16 sm[];
    const int x = blockIdx.x;          // 0..47
    const int y = blockIdx.y;          // 0..3
    const __nv_bfloat16 *Bh, *Bl;
    const float* bias;
    float* C;
    int N, tx;
    if (x < 32)      { tx = x;      Bh = g_qwhi; Bl = g_qwlo; bias = qb; C = g_qlin; N = HDIM; }
    else if (x < 40) { tx = x - 32; Bh = g_kwhi; Bl = g_kwlo; bias = kb; C = g_klin; N = KVDIM; }
    else             { tx = x - 40; Bh = g_vwhi; Bl = g_vwlo; bias = vb; C = g_vlin; N = KVDIM; }

    const size_t arow0 = (size_t)y * 128;
    const size_t brow0 = (size_t)tx * 128;
    gemm_core(g_hshi + arow0 * HDIM, g_hslo + arow0 * HDIM,
              Bh + brow0 * HDIM, Bl + brow0 * HDIM,
              bias + brow0, C + arow0 * N + brow0,
              HDIM, HDIM, N, HDIM, sm);
}

// ---------------- O projection ------------------------------------------------
__global__ __launch_bounds__(256) void gemm_single(
    const __nv_bfloat16* __restrict__ Ahi, const __nv_bfloat16* __restrict__ Alo,
    const __nv_bfloat16* __restrict__ Bhi, const __nv_bfloat16* __restrict__ Blo,
    const float* __restrict__ bias, float* __restrict__ C,
    int lda, int ldb, int ldc, int K)
{
    extern __shared__ __nv_bfloat16 sm[];
    const size_t arow0 = (size_t)(blockIdx.y * 128);
    const size_t brow0 = (size_t)(blockIdx.x * 128);
    gemm_core(Ahi + arow0 * lda, Alo + arow0 * lda,
              Bhi + brow0 * ldb, Blo + brow0 * ldb,
              bias ? bias + brow0 : nullptr, C + arow0 * ldc + brow0,
              lda, ldb, ldc, K, sm);
}

// ---------------- fused flash attention (2-stage, LDSM frags) -----------------
#define FK_PITCH 136
#define FV_PITCH 72
#define FBUF_ELEMS (2 * 64 * FK_PITCH + 2 * 128 * FV_PITCH)   // 35840 elems
#define S_FLASH (2 * FBUF_ELEMS * 2)                          // 143360 B

__global__ __launch_bounds__(256, 1) void flash_attn()
{
    extern __shared__ __nv_bfloat16 fsm[];

    const int bh = blockIdx.x;
    const int b = bh >> 5, h = bh & 31, kvh = h >> 2;
    const int bk = b * NKVH + kvh;
    const int tid = threadIdx.x, lane = tid & 31, w = tid >> 5;
    const int rq = w * 16 + (lane >> 2);
    const int q2 = (lane & 3) * 2;
    const int Lm = lane >> 3, Lr = lane & 7;
    const int kboff = ((Lm >> 1) * 8 + Lr) * FK_PITCH + (Lm & 1) * 8;  // K (B-type)
    const int voff  = ((Lm >> 1) * 8 + Lr) * FV_PITCH + (Lm & 1) * 8;  // V (B-type)
    const float isq = 0.08838834764831845f;
    const uint32_t fsm_u = smem_u32(fsm);

    const float* Q = g_q + (size_t)bh * QLEN * DHEAD;
    uint32_t qhi[8][4], qlo[8][4];
#pragma unroll
    for (int kk = 0; kk < 8; kk++) {
#pragma unroll
        for (int f = 0; f < 4; f++) {
            int rr = rq + ((f & 1) ? 8 : 0);
            int kc = kk * 16 + ((f & 2) ? 8 : 0) + q2;
            split2(Q[rr * DHEAD + kc], Q[rr * DHEAD + kc + 1], qhi[kk][f], qlo[kk][f]);
        }
    }

    const __nv_bfloat16* Khi = g_khi + (size_t)bk * KVSEQ * DHEAD;
    const __nv_bfloat16* Klo = g_klo + (size_t)bk * KVSEQ * DHEAD;
    const __nv_bfloat16* Vhi = g_vthi + (size_t)bk * DHEAD * KVSEQ;
    const __nv_bfloat16* Vlo = g_vtlo + (size_t)bk * DHEAD * KVSEQ;

    float m0 = NEGF, m1 = NEGF, l0 = 0.f, l1 = 0.f;
    float oacc[16][4];
#pragma unroll
    for (int td = 0; td < 16; td++)
#pragma unroll
        for (int i = 0; i < 4; i++) oacc[td][i] = 0.f;

#define F_STAGE(j, buf) do {                                               \
    __nv_bfloat16* dKhi = fsm + (buf) * FBUF_ELEMS;                        \
    __nv_bfloat16* dKlo = dKhi + 64 * FK_PITCH;                            \
    __nv_bfloat16* dVhi = dKhi + 2 * 64 * FK_PITCH;                        \
    __nv_bfloat16* dVlo = dVhi + 128 * FV_PITCH;                           \
    _Pragma("unroll")                                                      \
    for (int i = 0; i < 4; i++) {                                          \
        int u = i * 256 + tid;                                             \
        int n = u >> 4, kp = (u & 15) * 8;                                 \
        size_t go = (size_t)((j) * 64 + n) * DHEAD + kp;                   \
        cp16(dKhi + n * FK_PITCH + kp, Khi + go);                          \
        cp16(dKlo + n * FK_PITCH + kp, Klo + go);                          \
        int d = u >> 3, vp = (u & 7) * 8;                                  \
        size_t gv = (size_t)d * KVSEQ + (j) * 64 + vp;                     \
        cp16(dVhi + d * FV_PITCH + vp, Vhi + gv);                          \
        cp16(dVlo + d * FV_PITCH + vp, Vlo + gv);                          \
    }                                                                      \
    asm volatile("cp.async.commit_group;");                                \
} while (0)

    F_STAGE(0, 0);
    for (int j = 0; j < NBLK; j++) {
        if (j + 1 < NBLK) {
            F_STAGE(j + 1, (j + 1) & 1);
            asm volatile("cp.async.wait_group 1;");
        } else {
            asm volatile("cp.async.wait_group 0;");
        }
        __syncthreads();

        const uint32_t sKhi_u = fsm_u + (uint32_t)((j & 1) * FBUF_ELEMS) * 2u;
        const uint32_t sKlo_u = sKhi_u + 64u * FK_PITCH * 2u;
        const uint32_t sVhi_u = sKhi_u + 2u * 64u * FK_PITCH * 2u;
        const uint32_t sVlo_u = sVhi_u + 128u * FV_PITCH * 2u;

        float sacc[8][4];
#pragma unroll
        for (int nt = 0; nt < 8; nt++)
#pragma unroll
            for (int i = 0; i < 4; i++) sacc[nt][i] = 0.f;

#pragma unroll
        for (int kk = 0; kk < 8; kk++) {
#pragma unroll
            for (int np = 0; np < 4; np++) {
                uint32_t off = (uint32_t)((np * 16 * FK_PITCH + kk * 16 + kboff) * 2);
                uint32_t h0[2], h1[2], e0[2], e1[2];
                ldsm4(h0[0], h0[1], h1[0], h1[1], sKhi_u + off);
                ldsm4(e0[0], e0[1], e1[0], e1[1], sKlo_u + off);
                mma16816(sacc[2*np],     qhi[kk], h0);
                mma16816(sacc[2*np],     qhi[kk], e0);
                mma16816(sacc[2*np],     qlo[kk], h0);
                mma16816(sacc[2*np+1],   qhi[kk], h1);
                mma16816(sacc[2*np+1],   qhi[kk], e1);
                mma16816(sacc[2*np+1],   qlo[kk], h1);
            }
        }

#pragma unroll
        for (int nt = 0; nt < 8; nt++)
#pragma unroll
            for (int i = 0; i < 4; i++) sacc[nt][i] *= isq;
        if (j >= 66) {
            int jc = j * 64 - PASTLEN;
#pragma unroll
            for (int nt = 0; nt < 8; nt++) {
                int c = jc + nt * 8 + q2;
                if (c     > rq)     sacc[nt][0] = NEGF;
                if (c + 1 > rq)     sacc[nt][1] = NEGF;
                if (c     > rq + 8) sacc[nt][2] = NEGF;
                if (c + 1 > rq + 8) sacc[nt][3] = NEGF;
            }
        }

        float mx0 = NEGF, mx1 = NEGF;
#pragma unroll
        for (int nt = 0; nt < 8; nt++) {
            mx0 = fmaxf(mx0, fmaxf(sacc[nt][0], sacc[nt][1]));
            mx1 = fmaxf(mx1, fmaxf(sacc[nt][2], sacc[nt][3]));
        }
        mx0 = fmaxf(mx0, __shfl_xor_sync(0xffffffffu, mx0, 1));
        mx0 = fmaxf(mx0, __shfl_xor_sync(0xffffffffu, mx0, 2));
        mx1 = fmaxf(mx1, __shfl_xor_sync(0xffffffffu, mx1, 1));
        mx1 = fmaxf(mx1, __shfl_xor_sync(0xffffffffu, mx1, 2));

        float mn0 = fmaxf(m0, mx0), mn1 = fmaxf(m1, mx1);
        float a0 = __expf(m0 - mn0), a1 = __expf(m1 - mn1);

        float rs0 = 0.f, rs1 = 0.f;
#pragma unroll
        for (int nt = 0; nt < 8; nt++) {
            sacc[nt][0] = __expf(sacc[nt][0] - mn0);
            sacc[nt][1] = __expf(sacc[nt][1] - mn0);
            sacc[nt][2] = __expf(sacc[nt][2] - mn1);
            sacc[nt][3] = __expf(sacc[nt][3] - mn1);
            rs0 += sacc[nt][0] + sacc[nt][1];
            rs1 += sacc[nt][2] + sacc[nt][3];
        }
        rs0 += __shfl_xor_sync(0xffffffffu, rs0, 1);
        rs0 += __shfl_xor_sync(0xffffffffu, rs0, 2);
        rs1 += __shfl_xor_sync(0xffffffffu, rs1, 1);
        rs1 += __shfl_xor_sync(0xffffffffu, rs1, 2);
        l0 = l0 * a0 + rs0;
        l1 = l1 * a1 + rs1;
        m0 = mn0; m1 = mn1;

#pragma unroll
        for (int td = 0; td < 16; td++) {
            oacc[td][0] *= a0; oacc[td][1] *= a0;
            oacc[td][2] *= a1; oacc[td][3] *= a1;
        }

#pragma unroll
        for (int kk2 = 0; kk2 < 4; kk2++) {
            uint32_t phi[4], plo[4];
            split2(sacc[2 * kk2][0],     sacc[2 * kk2][1],     phi[0], plo[0]);
            split2(sacc[2 * kk2][2],     sacc[2 * kk2][3],     phi[1], plo[1]);
            split2(sacc[2 * kk2 + 1][0], sacc[2 * kk2 + 1][1], phi[2], plo[2]);
            split2(sacc[2 * kk2 + 1][2], sacc[2 * kk2 + 1][3], phi[3], plo[3]);
#pragma unroll
            for (int tp = 0; tp < 8; tp++) {
                uint32_t off = (uint32_t)((tp * 16 * FV_PITCH + kk2 * 16 + voff) * 2);
                uint32_t h0[2], h1[2], e0[2], e1[2];
                ldsm4(h0[0], h0[1], h1[0], h1[1], sVhi_u + off);
                ldsm4(e0[0], e0[1], e1[0], e1[1], sVlo_u + off);
                mma16816(oacc[2*tp],     phi, h0);
                mma16816(oacc[2*tp],     phi, e0);
                mma16816(oacc[2*tp],     plo, h0);
                mma16816(oacc[2*tp+1],   phi, h1);
                mma16816(oacc[2*tp+1],   phi, e1);
                mma16816(oacc[2*tp+1],   plo, h1);
            }
        }
        __syncthreads();
    }
#undef F_STAGE

    float inv0 = 1.f / l0, inv1 = 1.f / l1;
#pragma unroll
    for (int td = 0; td < 16; td++) {
        int cd = h * DHEAD + td * 8 + q2;
        {
            float x0 = oacc[td][0] * inv0, x1 = oacc[td][1] * inv0;
            uint32_t hi, lo;
            split2(x0, x1, hi, lo);
            size_t o = (size_t)(b * QLEN + rq) * HDIM + cd;
            *(uint32_t*)&g_aohi[o] = hi;
            *(uint32_t*)&g_aolo[o] = lo;
        }
        {
            float x0 = oacc[td][2] * inv1, x1 = oacc[td][3] * inv1;
            uint32_t hi, lo;
            split2(x0, x1, hi, lo);
            size_t o = (size_t)(b * QLEN + rq + 8) * HDIM + cd;
            *(uint32_t*)&g_aohi[o] = hi;
            *(uint32_t*)&g_aolo[o] = lo;
        }
    }
}

// ---------------- RoPE Q ------------------------------------------------------
__global__ __launch_bounds__(256) void rope_q_kernel()
{
    int idx = blockIdx.x * 256 + threadIdx.x;
    int d = idx & 127;
    int t = (idx >> 7) & 127;
    int h = (idx >> 14) & 31;
    int b = idx >> 19;
    size_t base = ((size_t)(b * QLEN + t)) * HDIM + (size_t)h * DHEAD;
    int i = d & 63;
    float inv = 1.0f / powf(1.0e6f, (float)(2 * i) / 128.0f);
    float ang = (float)(PASTLEN + t) * inv;
    float s, c;
    sincosf(ang, &s, &c);
    float x  = g_qlin[base + d];
    float xo = g_qlin[base + ((d < 64) ? d + 64 : d - 64)];
    g_q[idx] = (d < 64) ? (x * c - xo * s) : (x * c + xo * s);
}

// ---------------- merged RoPE-K + V-scatter (new tokens) ----------------------
__global__ __launch_bounds__(256) void rope_kv_kernel()
{
    int idx = blockIdx.x * 256 + threadIdx.x;      // 4*8*128*128
    {
        int d   = idx & 127;
        int t   = (idx >> 7) & 127;
        int kvh = (idx >> 14) & 7;
        int b   = idx >> 17;
        size_t base = ((size_t)(b * QLEN + t)) * KVDIM + (size_t)kvh * DHEAD;
        int i = d & 63;
        float inv = 1.0f / powf(1.0e6f, (float)(2 * i) / 128.0f);
        float ang = (float)(PASTLEN + t) * inv;
        float s, c;
        sincosf(ang, &s, &c);
        float x  = g_klin[base + d];
        float xo = g_klin[base + ((d < 64) ? d + 64 : d - 64)];
        float v  = (d < 64) ? (x * c - xo * s) : (x * c + xo * s);
        size_t o = (((size_t)(b * NKVH + kvh)) * KVSEQ + PASTLEN + t) * DHEAD + d;
        __nv_bfloat16 hi = __float2bfloat16(v);
        g_khi[o] = hi;
        g_klo[o] = __float2bfloat16(v - __bfloat162float(hi));
    }
    {
        int t   = idx & 127;
        int d   = (idx >> 7) & 127;
        int kvh = (idx >> 14) & 7;
        int b   = idx >> 17;
        float v = g_vlin[((size_t)(b * QLEN + t)) * KVDIM + kvh * DHEAD + d];
        size_t o = ((size_t)(b * NKVH + kvh) * DHEAD + d) * KVSEQ + PASTLEN + t;
        __nv_bfloat16 hi = __float2bfloat16(v);
        g_vthi[o] = hi;
        g_vtlo[o] = __float2bfloat16(v - __bfloat162float(hi));
    }
}

// ---------------- fp32 past copy (split) --------------------------------------
__global__ __launch_bounds__(256) void past_copy_kernel(
    const float* __restrict__ kfp, const float* __restrict__ vfp)
{
    int idx = blockIdx.x * 256 + threadIdx.x;      // 32*128*128
    int d  = idx & 127;
    int r  = (idx >> 7) & 127;
    int bk = idx >> 14;
    size_t src = ((size_t)bk * RESLEN + r) * DHEAD + d;
    if (blockIdx.y == 0) {
        float v = kfp[src];
        size_t o = ((size_t)bk * KVSEQ + NQK + r) * DHEAD + d;
        __nv_bfloat16 hi = __float2bfloat16(v);
        g_khi[o] = hi;
        g_klo[o] = __float2bfloat16(v - __bfloat162float(hi));
    } else {
        float v = vfp[src];
        size_t o = ((size_t)bk * DHEAD + d) * KVSEQ + NQK + r;
        __nv_bfloat16 hi = __float2bfloat16(v);
        g_vthi[o] = hi;
        g_vtlo[o] = __float2bfloat16(v - __bfloat162float(hi));
    }
}

// ---------------- dequant 2-bit K -> split K cache ----------------------------
__global__ __launch_bounds__(256) void dequant_k_kernel(
    const int* __restrict__ kq, const float* __restrict__ ks,
    const float* __restrict__ km)
{
    int idx = blockIdx.x * 256 + threadIdx.x;
    int d  = idx & 127;
    int n  = (idx >> 7) & 4095;
    int bk = idx >> 19;
    unsigned word = (unsigned)kq[((size_t)bk * DHEAD + d) * (NQK / 16) + (n >> 4)];
    float code = (float)((word >> ((n & 15) * 2)) & 3u);
    size_t sidx = ((size_t)bk * DHEAD + d) * (NQK / 64) + (n >> 6);
    float v = code * ks[sidx] + km[sidx];
    size_t o = ((size_t)bk * KVSEQ + n) * DHEAD + d;
    __nv_bfloat16 hi = __float2bfloat16(v);
    g_khi[o] = hi;
    g_klo[o] = __float2bfloat16(v - __bfloat162float(hi));
}

// ---------------- dequant 2-bit V -> split V^T cache --------------------------
__global__ __launch_bounds__(256) void dequant_v_kernel(
    const int* __restrict__ vq, const float* __restrict__ vs,
    const float* __restrict__ vm)
{
    int idx = blockIdx.x * 256 + threadIdx.x;
    int n  = idx & 4095;
    int d  = (idx >> 12) & 127;
    int bk = idx >> 19;
    unsigned word = (unsigned)vq[((size_t)bk * NQK + n) * (DHEAD / 16) + (d >> 4)];
    float code = (float)((word >> ((d & 15) * 2)) & 3u);
    size_t sidx = ((size_t)bk * NQK + n) * (DHEAD / 64) + (d >> 6);
    float v = code * vs[sidx] + vm[sidx];
    size_t o = ((size_t)bk * DHEAD + d) * KVSEQ + n;
    __nv_bfloat16 hi = __float2bfloat16(v);
    g_vthi[o] = hi;
    g_vtlo[o] = __float2bfloat16(v - __bfloat162float(hi));
}

// ---------------- host launch --------------------------------------------------
extern "C" void kernel_launch(void* const* d_in, const int* in_sizes, int n_in,
                              void* d_out, int out_size)
{
    (void)in_sizes; (void)n_in; (void)out_size;
    const float* hs  = (const float*)d_in[0];
    const float* qw  = (const float*)d_in[1];
    const float* qb  = (const float*)d_in[2];
    const float* kw  = (const float*)d_in[3];
    const float* kb  = (const float*)d_in[4];
    const float* vw  = (const float*)d_in[5];
    const float* vb  = (const float*)d_in[6];
    const float* ow  = (const float*)d_in[7];
    const int*   kqt = (const int*)  d_in[8];
    const float* kst = (const float*)d_in[9];
    const float* kmt = (const float*)d_in[10];
    const float* kfp = (const float*)d_in[11];
    const int*   vq  = (const int*)  d_in[12];
    const float* vs  = (const float*)d_in[13];
    const float* vm  = (const float*)d_in[14];
    const float* vfp = (const float*)d_in[15];
    float* out = (float*)d_out;

    __nv_bfloat16 *hshi, *hslo, *qwhi, *qwlo, *kwhi, *kwlo, *vwhi, *vwlo;
    __nv_bfloat16 *owhi, *owlo, *aohi, *aolo;
    cudaGetSymbolAddress((void**)&hshi, g_hshi);
    cudaGetSymbolAddress((void**)&hslo, g_hslo);
    cudaGetSymbolAddress((void**)&qwhi, g_qwhi);
    cudaGetSymbolAddress((void**)&qwlo, g_qwlo);
    cudaGetSymbolAddress((void**)&kwhi, g_kwhi);
    cudaGetSymbolAddress((void**)&kwlo, g_kwlo);
    cudaGetSymbolAddress((void**)&vwhi, g_vwhi);
    cudaGetSymbolAddress((void**)&vwlo, g_vwlo);
    cudaGetSymbolAddress((void**)&owhi, g_owhi);
    cudaGetSymbolAddress((void**)&owlo, g_owlo);
    cudaGetSymbolAddress((void**)&aohi, g_aohi);
    cudaGetSymbolAddress((void**)&aolo, g_aolo);

    cudaFuncSetAttribute(proj_qkv,    cudaFuncAttributeMaxDynamicSharedMemorySize, S_GEMM);
    cudaFuncSetAttribute(gemm_single, cudaFuncAttributeMaxDynamicSharedMemorySize, S_GEMM);
    cudaFuncSetAttribute(flash_attn,  cudaFuncAttributeMaxDynamicSharedMemorySize, S_FLASH);

    // lazy-init side stream + fork/join events
    static cudaStream_t sB = nullptr;
    static cudaEvent_t evFork = nullptr, evJoin = nullptr;
    if (sB == nullptr) {
        cudaStreamCreateWithFlags(&sB, cudaStreamNonBlocking);
        cudaEventCreateWithFlags(&evFork, cudaEventDisableTiming);
        cudaEventCreateWithFlags(&evJoin, cudaEventDisableTiming);
    }

    dim3 blk(256);

    // fork: input-only work onto side stream
    cudaEventRecord(evFork, 0);
    cudaStreamWaitEvent(sB, evFork, 0);
    dequant_k_kernel<<<(32 * NQK * DHEAD) / 256, blk, 0, sB>>>(kqt, kst, kmt);
    dequant_v_kernel<<<(32 * NQK * DHEAD) / 256, blk, 0, sB>>>(vq, vs, vm);
    past_copy_kernel<<<dim3((32 * RESLEN * DHEAD) / 256, 2), blk, 0, sB>>>(kfp, vfp);
    split_f32<<<(HDIM * HDIM) / 1024, blk, 0, sB>>>(ow, owhi, owlo);
    cudaEventRecord(evJoin, sB);

    // main stream: proj-chain splits
    split_f32<<<(TOK * HDIM) / 1024, blk>>>(hs, hshi, hslo);
    split_f32<<<(HDIM * HDIM) / 1024, blk>>>(qw, qwhi, qwlo);
    split_f32<<<(KVDIM * HDIM) / 1024, blk>>>(kw, kwhi, kwlo);
    split_f32<<<(KVDIM * HDIM) / 1024, blk>>>(vw, vwhi, vwlo);

    // merged QKV projections
    proj_qkv<<<dim3(48, 4), blk, S_GEMM>>>(qb, kb, vb);

    // RoPE
    rope_q_kernel<<<(TOK * HDIM) / 256, blk>>>();
    rope_kv_kernel<<<(TOK * KVDIM) / 256, blk>>>();

    // join
    cudaStreamWaitEvent(0, evJoin, 0);

    // fused attention
    flash_attn<<<BATCH * NHEAD, blk, S_FLASH>>>();

    // output projection
    gemm_single<<<dim3(32, 4), blk, S_GEMM>>>(aohi, aolo, owhi, owlo, nullptr, out, HDIM, HDIM, HDIM, HDIM);
}